// round 15
// baseline (speedup 1.0000x reference)
#include <cuda_runtime.h>
#include <cuda_fp16.h>
#include <math.h>
#include <stdint.h>

#define HW 16384
#define PR 132            // padded row stride (words)
#define PCH (130*132)     // padded per-channel-pair words (17160)

// ---------------- scratch (device globals; zero-initialized) ----------------
__device__ __align__(16) unsigned g_xp [4ll*256*PCH];  // x, half2 ch-pairs, padded
__device__ float g_t1 [4ll*256*HW];                    // conv1 raw out (f32)
__device__ __align__(16) unsigned g_t1p[4ll*128*PCH];  // GN1+ReLU half2 pairs
__device__ float g_t2 [4ll*128*HW];
__device__ __align__(16) unsigned g_t2p[4ll*64*PCH];
__device__ float g_t3 [4ll*64*HW];
__device__ float g_t3t[4ll*HW*64];                     // GN3+ReLU, channel-last
__device__ __align__(16) unsigned g_w1t[256*512*9/2];  // [ocG][chunk][9][8][64] half2
__device__ __align__(16) unsigned g_w2t[128*256*9/2];
__device__ __align__(16) unsigned g_w3t[64*128*9/2];
__device__ float g_part1[4*8*2];                       // (sum, sumsq) per (b, group)
__device__ float g_part2[4*4*2];
__device__ float g_part3[4*4*2];
__device__ float g_sums[4*20*64];
__device__ float g_cnts[4*20];

// ---------------- helpers ----------------------------------------------------
__device__ __forceinline__ unsigned packh2(float a, float b) {
    __half2 h = __floats2half2_rn(a, b);
    return *(unsigned*)&h;
}
__device__ __forceinline__ void cpa16(uint32_t d, const void* s) {
    asm volatile("cp.async.ca.shared.global [%0], [%1], 16;" :: "r"(d), "l"(s));
}
__device__ __forceinline__ void cpa8(uint32_t d, const void* s) {
    asm volatile("cp.async.ca.shared.global [%0], [%1], 8;" :: "r"(d), "l"(s));
}
__device__ __forceinline__ void mma_f16(float c[4],
                                        unsigned a0, unsigned a1, unsigned a2, unsigned a3,
                                        unsigned b0, unsigned b1) {
    asm volatile(
        "mma.sync.aligned.m16n8k16.row.col.f32.f16.f16.f32 "
        "{%0,%1,%2,%3}, {%4,%5,%6,%7}, {%8,%9}, {%0,%1,%2,%3};"
        : "+f"(c[0]), "+f"(c[1]), "+f"(c[2]), "+f"(c[3])
        : "r"(a0), "r"(a1), "r"(a2), "r"(a3), "r"(b0), "r"(b1));
}

// ---------------- zero accumulators -----------------------------------------
__global__ void zero_kernel() {
    int tid = threadIdx.x;
    for (int i = tid; i < 4*20*64; i += 256) g_sums[i] = 0.f;
    if (tid < 80) g_cnts[tid] = 0.f;
    if (tid < 64) g_part1[tid] = 0.f;
    if (tid < 32) { g_part2[tid] = 0.f; g_part3[tid] = 0.f; }
}

// ------- x -> half2 channel pairs, interior only (padding stays zero) -------
__global__ void prep_x(const float* __restrict__ x) {
    int p = blockIdx.x;                    // b*256 + cp
    int b = p >> 8, cp = p & 255;
    const float* s0 = x + ((size_t)b * 512 + 2 * cp) * HW;
    const float* s1 = s0 + HW;
    unsigned* dst = g_xp + (size_t)p * PCH;
    for (int i = threadIdx.x; i < HW; i += 256) {
        int y = i >> 7, xx = i & 127;
        dst[(y + 1) * PR + xx + 1] = packh2(s0[i], s1[i]);
    }
}

// -------- weights -> [ocG][chunk16][kappa(9)][iclp(8)][oc(64)] half2 --------
__global__ void prep_w(const float* __restrict__ w, unsigned* __restrict__ dst,
                       int IC, int total) {
    int d = blockIdx.x * 256 + threadIdx.x;
    if (d >= total) return;
    int oc_in = d & 63;
    int t = d >> 6;
    int iclp = t & 7; t >>= 3;
    int kappa = t % 9; t /= 9;
    int nch = IC >> 4;
    int chunk = t % nch;
    int ocG = t / nch;
    int oc = ocG * 64 + oc_in;
    int ic = chunk * 16 + 2 * iclp;
    float v0 = w[((size_t)oc * IC + ic) * 9 + kappa];
    float v1 = w[((size_t)oc * IC + ic + 1) * 9 + kappa];
    dst[d] = packh2(v0, v1);
}

// ---------------- implicit-GEMM conv, fp16 m16n8k16, cp.async 2-buffer ------
// Block 512 thr = 16 warps (8M x 2N). Tile: 512 px (32 tall x 16 wide) x 64 OC.
// Warp tile: 64 px x 32 OC (unchanged from verified R10 kernel).
// K chunk = 16 input channels = 9 k16-steps (one 3x3 tap per step).
#define SMEM_WORDS (2*5440 + 2*5184)
template<int IC, int OC, int OCPG>
__global__ __launch_bounds__(512, 1)
void conv_mma(const unsigned* __restrict__ inp,  // [b][icp][PCH] half2
              const unsigned* __restrict__ wt,   // [ocG][IC/16][4608] half2
              const float* __restrict__ bias,
              float* __restrict__ out,           // [b][oc][HW] f32
              float* __restrict__ part)          // [B*G][2]
{
    extern __shared__ unsigned sm[];
    unsigned* s_in = sm;                 // 2 x 8 planes x 34 x 20
    unsigned* s_w  = sm + 2 * 5440;      // 2 x 9 x 8 x 72

    const int tid = threadIdx.x, wid = tid >> 5, lane = tid & 31;
    const int lq = lane & 3, lr = lane >> 2;
    const int warpM = wid & 7, warpN = wid >> 3;
    const int tileY = blockIdx.x >> 3, tileX = blockIdx.x & 7;
    const int y0 = tileY * 32, x0 = tileX * 16;
    const int ocG = blockIdx.y;
    const int b = blockIdx.z;
    const unsigned* inb = inp + (size_t)b * (IC / 2) * PCH;
    const unsigned* wbase = wt + (size_t)ocG * (IC / 16) * 4608;
    uint32_t s_in_b = (uint32_t)__cvta_generic_to_shared(s_in);
    uint32_t s_w_b  = (uint32_t)__cvta_generic_to_shared(s_w);

    float C[4][4][4] = {};

    const int NCH = IC / 16;
    auto stage = [&](int ch, int buf) {
        uint32_t sbase = s_in_b + buf * 5440 * 4;
        const unsigned* gch = inb + (size_t)ch * 8 * PCH;
        for (int o = tid; o < 1360; o += 512) {
            int row = o / 5, piece = o - row * 5;
            int iclp = row / 34, yy = row - iclp * 34;
            const unsigned* src = gch + (size_t)iclp * PCH + (y0 + yy) * PR + x0 + piece * 4;
            uint32_t dst = sbase + (iclp * 680 + yy * 20 + piece * 4) * 4;
            if (piece < 4) cpa16(dst, src); else cpa8(dst, src);
        }
        uint32_t swb = s_w_b + buf * 5184 * 4;
        const unsigned* wsrc = wbase + (size_t)ch * 4608;
        for (int j = tid; j < 1152; j += 512) {
            int r = j >> 4, c4 = (j & 15) * 4;
            cpa16(swb + (r * 72 + c4) * 4, wsrc + j * 4);
        }
    };

    stage(0, 0);
    asm volatile("cp.async.commit_group;");
#pragma unroll 1
    for (int ch = 0; ch < NCH; ch++) {
        int cur = ch & 1;
        if (ch + 1 < NCH) stage(ch + 1, cur ^ 1);
        asm volatile("cp.async.commit_group;");
        asm volatile("cp.async.wait_group 1;");
        __syncthreads();
        const unsigned* bi = s_in + cur * 5440;
        const unsigned* bw = s_w + cur * 5184;
#pragma unroll
        for (int kappa = 0; kappa < 9; kappa++) {
            unsigned bf[4][2];
#pragma unroll
            for (int g = 0; g < 4; g++) {
                int ncol = warpN * 32 + g * 8 + lr;
                bf[g][0] = bw[kappa * 576 + lq * 72 + ncol];
                bf[g][1] = bw[kappa * 576 + (lq + 4) * 72 + ncol];
            }
            const int ky = kappa / 3, kx = kappa % 3;
#pragma unroll
            for (int f = 0; f < 4; f++) {
                const int base = (warpM * 4 + f + ky) * 20 + kx;
                unsigned a0 = bi[lq * 680 + base + lr];
                unsigned a1 = bi[lq * 680 + base + lr + 8];
                unsigned a2 = bi[(lq + 4) * 680 + base + lr];
                unsigned a3 = bi[(lq + 4) * 680 + base + lr + 8];
#pragma unroll
                for (int g = 0; g < 4; g++)
                    mma_f16(C[f][g], a0, a1, a2, a3, bf[g][0], bf[g][1]);
            }
        }
        __syncthreads();
    }

    // ---- epilogue: store + partial GN stats ----
    constexpr int G = OC / OCPG;
    float s0 = 0.f, q0 = 0.f, s1 = 0.f, q1 = 0.f;
#pragma unroll
    for (int f = 0; f < 4; f++) {
        const int gy = y0 + warpM * 4 + f;
#pragma unroll
        for (int g = 0; g < 4; g++) {
            const int oc = ocG * 64 + warpN * 32 + g * 8 + 2 * lq;
            const float b0 = bias[oc], b1v = bias[oc + 1];
            float v0 = C[f][g][0] + b0, v1 = C[f][g][1] + b1v;
            float v2 = C[f][g][2] + b0, v3 = C[f][g][3] + b1v;
            float* o0 = out + ((size_t)b * OC + oc) * HW + gy * 128 + x0;
            o0[lr] = v0; o0[HW + lr] = v1; o0[lr + 8] = v2; o0[HW + lr + 8] = v3;
            if (OCPG == 16 && g >= 2) {
                s1 += v0 + v1 + v2 + v3;
                q1 += v0 * v0 + v1 * v1 + v2 * v2 + v3 * v3;
            } else {
                s0 += v0 + v1 + v2 + v3;
                q0 += v0 * v0 + v1 * v1 + v2 * v2 + v3 * v3;
            }
        }
    }
#pragma unroll
    for (int o = 16; o; o >>= 1) {
        s0 += __shfl_xor_sync(0xffffffffu, s0, o);
        q0 += __shfl_xor_sync(0xffffffffu, q0, o);
        if (OCPG == 16) {
            s1 += __shfl_xor_sync(0xffffffffu, s1, o);
            q1 += __shfl_xor_sync(0xffffffffu, q1, o);
        }
    }
    if (lane == 0) {
        int gidx = (ocG * 64 + warpN * 32) / OCPG;
        atomicAdd(&part[(b * G + gidx) * 2],     s0);
        atomicAdd(&part[(b * G + gidx) * 2 + 1], q0);
        if (OCPG == 16) {
            atomicAdd(&part[(b * G + gidx + 1) * 2],     s1);
            atomicAdd(&part[(b * G + gidx + 1) * 2 + 1], q1);
        }
    }
}

// ------- GN+ReLU apply -> half2 pairs, interior only (padding stays 0) ------
template<int C_, int G>
__global__ void gn_apply(const float* __restrict__ t, const float* __restrict__ part,
                         const float* __restrict__ gw, const float* __restrict__ gb,
                         unsigned* __restrict__ outp)
{
    int p = blockIdx.x;                    // b*(C_/2) + cp
    int b = p / (C_ / 2), cp = p - b * (C_ / 2);
    int c0 = 2 * cp, c1 = c0 + 1;
    int g = c0 / (C_ / G);
    float n = (float)(C_ / G) * (float)HW;
    float S = part[(b * G + g) * 2], S2 = part[(b * G + g) * 2 + 1];
    float mean = S / n;
    float rs = rsqrtf(S2 / n - mean * mean + 1e-5f);
    float sc0 = rs * gw[c0], sh0 = gb[c0] - mean * sc0;
    float sc1 = rs * gw[c1], sh1 = gb[c1] - mean * sc1;
    const float* src0 = t + ((size_t)b * C_ + c0) * HW;
    const float* src1 = src0 + HW;
    unsigned* dst = outp + (size_t)p * PCH;
    for (int i = threadIdx.x; i < HW; i += 256) {
        int y = i >> 7, xx = i & 127;
        dst[(y + 1) * PR + xx + 1] = packh2(fmaxf(0.f, src0[i] * sc0 + sh0),
                                            fmaxf(0.f, src1[i] * sc1 + sh1));
    }
}

// ---------------- GN3+ReLU apply + transpose to [b][p][64] ------------------
__global__ void gn_apply3t(const float* __restrict__ g3w, const float* __restrict__ g3b) {
    __shared__ float smT[64 * 65];
    int b = blockIdx.y;
    int p0 = blockIdx.x * 64;
    int tid = threadIdx.x;
#pragma unroll
    for (int i = 0; i < 16; i++) {
        int idx = tid + i * 256;
        int c = idx >> 6, pl = idx & 63;
        int g = c >> 4;
        float S = g_part3[(b * 4 + g) * 2], S2 = g_part3[(b * 4 + g) * 2 + 1];
        float n = 16.f * (float)HW;
        float mean = S / n;
        float rs = rsqrtf(S2 / n - mean * mean + 1e-5f);
        float sc = rs * g3w[c], sh = g3b[c] - mean * sc;
        smT[c * 65 + pl] = fmaxf(0.f, g_t3[((size_t)b * 64 + c) * HW + p0 + pl] * sc + sh);
    }
    __syncthreads();
    float* dst = g_t3t + ((size_t)b * HW + p0) * 64;
#pragma unroll
    for (int i = 0; i < 16; i++) {
        int idx = tid + i * 256;
        int pl = idx >> 6, c = idx & 63;
        dst[pl * 64 + c] = smT[c * 65 + pl];
    }
}

// ---------------- masked segment-sum pooling --------------------------------
__global__ void pool_kernel(const int* __restrict__ masks) {
    __shared__ float s_sum[20][64];
    __shared__ float s_cnt[20];
    const int tid = threadIdx.x;
    const int lane = tid & 31, w = tid >> 5;
    const int b = blockIdx.y;
    const int base = blockIdx.x * 1024;

    for (int i = tid; i < 20 * 64; i += 256) ((float*)s_sum)[i] = 0.f;
    if (tid < 20) s_cnt[tid] = 0.f;
    __syncthreads();

    const int* mp = masks + b * HW + base;
    for (int p = w; p < 1024; p += 8) {
        int id = mp[p];
        if (id > 0) {
            const float* hp = g_t3t + ((size_t)b * HW + base + p) * 64;
            atomicAdd(&s_sum[id - 1][lane],      hp[lane]);
            atomicAdd(&s_sum[id - 1][lane + 32], hp[lane + 32]);
            if (lane == 0) atomicAdd(&s_cnt[id - 1], 1.f);
        }
    }
    __syncthreads();
    for (int i = tid; i < 20 * 64; i += 256) {
        int k = i >> 6, c = i & 63;
        atomicAdd(&g_sums[((size_t)b * 20 + k) * 64 + c], s_sum[k][c]);
    }
    if (tid < 20) atomicAdd(&g_cnts[b * 20 + tid], s_cnt[tid]);
}

// ---------------- heads ------------------------------------------------------
__global__ void head_kernel(const float* __restrict__ wb, const float* __restrict__ bb,
                            const float* __restrict__ wc, const float* __restrict__ bc,
                            float* __restrict__ out)
{
    int t = threadIdx.x;
    if (t >= 640) return;
    int b = t / 160;
    int rem = t - b * 160;
    int k = rem >> 3, o = rem & 7;
    float inv = 1.f / (g_cnts[b * 20 + k] + 1e-6f);
    const float* sp = &g_sums[((size_t)b * 20 + k) * 64];
    if (o < 7) {
        float s = bb[o];
        for (int c = 0; c < 64; c++) s += sp[c] * inv * wb[o * 64 + c];
        out[(b * 20 + k) * 7 + o] = s;
    } else {
        float s = bc[0];
        for (int c = 0; c < 64; c++) s += sp[c] * inv * wc[c];
        out[560 + b * 20 + k] = 1.f / (1.f + expf(-s));
    }
}

// ---------------- launch ----------------------------------------------------
extern "C" void kernel_launch(void* const* d_in, const int* in_sizes, int n_in,
                              void* d_out, int out_size)
{
    const float* x   = (const float*)d_in[0];
    const int*   mk  = (const int*)  d_in[1];
    const float* w1  = (const float*)d_in[2];
    const float* b1  = (const float*)d_in[3];
    const float* g1w = (const float*)d_in[4];
    const float* g1b = (const float*)d_in[5];
    const float* w2  = (const float*)d_in[6];
    const float* b2  = (const float*)d_in[7];
    const float* g2w = (const float*)d_in[8];
    const float* g2b = (const float*)d_in[9];
    const float* w3  = (const float*)d_in[10];
    const float* b3  = (const float*)d_in[11];
    const float* g3w = (const float*)d_in[12];
    const float* g3b = (const float*)d_in[13];
    const float* wb  = (const float*)d_in[14];
    const float* bb  = (const float*)d_in[15];
    const float* wc  = (const float*)d_in[16];
    const float* bc  = (const float*)d_in[17];
    float* out = (float*)d_out;

    unsigned *xp, *t1p, *t2p, *w1t, *w2t, *w3t;
    float *t1, *t2, *t3, *p1, *p2, *p3;
    cudaGetSymbolAddress((void**)&xp,  g_xp);
    cudaGetSymbolAddress((void**)&t1,  g_t1);
    cudaGetSymbolAddress((void**)&t1p, g_t1p);
    cudaGetSymbolAddress((void**)&t2,  g_t2);
    cudaGetSymbolAddress((void**)&t2p, g_t2p);
    cudaGetSymbolAddress((void**)&t3,  g_t3);
    cudaGetSymbolAddress((void**)&w1t, g_w1t);
    cudaGetSymbolAddress((void**)&w2t, g_w2t);
    cudaGetSymbolAddress((void**)&w3t, g_w3t);
    cudaGetSymbolAddress((void**)&p1,  g_part1);
    cudaGetSymbolAddress((void**)&p2,  g_part2);
    cudaGetSymbolAddress((void**)&p3,  g_part3);

    const int SMEMB = SMEM_WORDS * 4;
    cudaFuncSetAttribute(conv_mma<512, 256, 32>, cudaFuncAttributeMaxDynamicSharedMemorySize, SMEMB);
    cudaFuncSetAttribute(conv_mma<256, 128, 32>, cudaFuncAttributeMaxDynamicSharedMemorySize, SMEMB);
    cudaFuncSetAttribute(conv_mma<128, 64, 16>,  cudaFuncAttributeMaxDynamicSharedMemorySize, SMEMB);

    zero_kernel<<<1, 256>>>();

    prep_x<<<4 * 256, 256>>>(x);
    prep_w<<<(256 * 512 * 9 / 2 + 255) / 256, 256>>>(w1, w1t, 512, 256 * 512 * 9 / 2);
    prep_w<<<(128 * 256 * 9 / 2 + 255) / 256, 256>>>(w2, w2t, 256, 128 * 256 * 9 / 2);
    prep_w<<<(64 * 128 * 9 / 2 + 255) / 256, 256>>>(w3, w3t, 128, 64 * 128 * 9 / 2);

    conv_mma<512, 256, 32><<<dim3(32, 4, 4), 512, SMEMB>>>(xp, w1t, b1, t1, p1);
    gn_apply<256, 8><<<4 * 128, 256>>>(t1, p1, g1w, g1b, t1p);

    conv_mma<256, 128, 32><<<dim3(32, 2, 4), 512, SMEMB>>>(t1p, w2t, b2, t2, p2);
    gn_apply<128, 4><<<4 * 64, 256>>>(t2, p2, g2w, g2b, t2p);

    conv_mma<128, 64, 16><<<dim3(32, 1, 4), 512, SMEMB>>>(t2p, w3t, b3, t3, p3);
    gn_apply3t<<<dim3(256, 4), 256>>>(g3w, g3b);

    pool_kernel<<<dim3(16, 4), 256>>>(mk);
    head_kernel<<<1, 640>>>(wb, bb, wc, bc, out);
}

// round 16
// speedup vs baseline: 1.1734x; 1.1734x over previous
#include <cuda_runtime.h>
#include <cuda_fp16.h>
#include <math.h>
#include <stdint.h>

#define HW 16384
#define PR 132            // padded row stride (words)
#define PCH (130*132)     // padded per-channel-pair words (17160)

// ---------------- scratch (device globals; zero-initialized) ----------------
__device__ __align__(16) unsigned g_xp [4ll*256*PCH];  // x, half2 ch-pairs, padded
__device__ float g_t1 [4ll*256*HW];                    // conv1 raw out (f32)
__device__ __align__(16) unsigned g_t1p[4ll*128*PCH];  // GN1+ReLU half2 pairs
__device__ float g_t2 [4ll*128*HW];
__device__ __align__(16) unsigned g_t2p[4ll*64*PCH];
__device__ float g_t3 [4ll*64*HW];
__device__ float g_t3t[4ll*HW*64];                     // GN3+ReLU, channel-last
__device__ __align__(16) unsigned g_w1t[256*512*9/2];  // [ocG][chunk][9][8][64] half2
__device__ __align__(16) unsigned g_w2t[128*256*9/2];
__device__ __align__(16) unsigned g_w3t[64*128*9/2];
__device__ float g_part1[4*8*2];                       // (sum, sumsq) per (b, group)
__device__ float g_part2[4*4*2];
__device__ float g_part3[4*4*2];
__device__ float g_sums[4*20*64];
__device__ float g_cnts[4*20];

// ---------------- helpers ----------------------------------------------------
__device__ __forceinline__ unsigned packh2(float a, float b) {
    __half2 h = __floats2half2_rn(a, b);
    return *(unsigned*)&h;
}
__device__ __forceinline__ void cpa16(uint32_t d, const void* s) {
    asm volatile("cp.async.ca.shared.global [%0], [%1], 16;" :: "r"(d), "l"(s));
}
__device__ __forceinline__ void cpa8(uint32_t d, const void* s) {
    asm volatile("cp.async.ca.shared.global [%0], [%1], 8;" :: "r"(d), "l"(s));
}
__device__ __forceinline__ void mma_f16(float c[4],
                                        unsigned a0, unsigned a1, unsigned a2, unsigned a3,
                                        unsigned b0, unsigned b1) {
    asm volatile(
        "mma.sync.aligned.m16n8k16.row.col.f32.f16.f16.f32 "
        "{%0,%1,%2,%3}, {%4,%5,%6,%7}, {%8,%9}, {%0,%1,%2,%3};"
        : "+f"(c[0]), "+f"(c[1]), "+f"(c[2]), "+f"(c[3])
        : "r"(a0), "r"(a1), "r"(a2), "r"(a3), "r"(b0), "r"(b1));
}

// ---------------- weight repack (device helper; indexing verified R10) ------
__device__ __forceinline__ void prep_w_elem(const float* __restrict__ w,
                                            unsigned* __restrict__ dst,
                                            int IC, int d) {
    int oc_in = d & 63;
    int t = d >> 6;
    int iclp = t & 7; t >>= 3;
    int kappa = t % 9; t /= 9;
    int nch = IC >> 4;
    int chunk = t % nch;
    int ocG = t / nch;
    int oc = ocG * 64 + oc_in;
    int ic = chunk * 16 + 2 * iclp;
    float v0 = w[((size_t)oc * IC + ic) * 9 + kappa];
    float v1 = w[((size_t)oc * IC + ic + 1) * 9 + kappa];
    dst[d] = packh2(v0, v1);
}

// ------ merged prep: zero accumulators + x-pack + 3 weight repacks ----------
// blocks [0,1024): prep_x  (b*256+cp per block)
// [1024, 3328): w1   (2304 blocks)
// [3328, 3904): w2   (576 blocks)
// [3904, 4048): w3   (144 blocks)
// [4048]: zero accumulators
__global__ void prep_all(const float* __restrict__ x,
                         const float* __restrict__ w1,
                         const float* __restrict__ w2,
                         const float* __restrict__ w3)
{
    int blk = blockIdx.x;
    int tid = threadIdx.x;
    if (blk < 1024) {
        int b = blk >> 8, cp = blk & 255;
        const float* s0 = x + ((size_t)b * 512 + 2 * cp) * HW;
        const float* s1 = s0 + HW;
        unsigned* dst = g_xp + (size_t)blk * PCH;
        for (int i = tid; i < HW; i += 256) {
            int y = i >> 7, xx = i & 127;
            dst[(y + 1) * PR + xx + 1] = packh2(s0[i], s1[i]);
        }
    } else if (blk < 3328) {
        int d = (blk - 1024) * 256 + tid;
        prep_w_elem(w1, g_w1t, 512, d);
    } else if (blk < 3904) {
        int d = (blk - 3328) * 256 + tid;
        prep_w_elem(w2, g_w2t, 256, d);
    } else if (blk < 4048) {
        int d = (blk - 3904) * 256 + tid;
        prep_w_elem(w3, g_w3t, 128, d);
    } else {
        for (int i = tid; i < 4*20*64; i += 256) g_sums[i] = 0.f;
        if (tid < 80) g_cnts[tid] = 0.f;
        if (tid < 64) g_part1[tid] = 0.f;
        if (tid < 32) { g_part2[tid] = 0.f; g_part3[tid] = 0.f; }
    }
}

// ---------------- implicit-GEMM conv, fp16 m16n8k16, cp.async 2-buffer ------
// (exact R10 configuration: 256 thr = 8 warps (4M x 2N), occupancy 2,
//  tile 256 px (16x16) x 64 OC, warp tile 64 px x 32 OC,
//  K chunk = 16 input channels = 9 k16-steps)
#define SMEM_WORDS (2*2880 + 2*5184)
template<int IC, int OC, int OCPG>
__global__ __launch_bounds__(256, 2)
void conv_mma(const unsigned* __restrict__ inp,  // [b][icp][PCH] half2
              const unsigned* __restrict__ wt,   // [ocG][IC/16][4608] half2
              const float* __restrict__ bias,
              float* __restrict__ out,           // [b][oc][HW] f32
              float* __restrict__ part)          // [B*G][2]
{
    extern __shared__ unsigned sm[];
    unsigned* s_in = sm;                 // 2 x 8 planes x 18 x 20
    unsigned* s_w  = sm + 2 * 2880;      // 2 x 9 x 8 x 72

    const int tid = threadIdx.x, wid = tid >> 5, lane = tid & 31;
    const int lq = lane & 3, lr = lane >> 2;
    const int warpM = wid & 3, warpN = wid >> 2;
    const int tileY = blockIdx.x >> 3, tileX = blockIdx.x & 7;
    const int y0 = tileY * 16, x0 = tileX * 16;
    const int ocG = blockIdx.y;
    const int b = blockIdx.z;
    const unsigned* inb = inp + (size_t)b * (IC / 2) * PCH;
    const unsigned* wbase = wt + (size_t)ocG * (IC / 16) * 4608;
    uint32_t s_in_b = (uint32_t)__cvta_generic_to_shared(s_in);
    uint32_t s_w_b  = (uint32_t)__cvta_generic_to_shared(s_w);

    float C[4][4][4] = {};

    const int NCH = IC / 16;
    auto stage = [&](int ch, int buf) {
        uint32_t sbase = s_in_b + buf * 2880 * 4;
        const unsigned* gch = inb + (size_t)ch * 8 * PCH;
        for (int o = tid; o < 720; o += 256) {
            int row = o / 5, piece = o - row * 5;
            int iclp = row / 18, yy = row - iclp * 18;
            const unsigned* src = gch + (size_t)iclp * PCH + (y0 + yy) * PR + x0 + piece * 4;
            uint32_t dst = sbase + (iclp * 360 + yy * 20 + piece * 4) * 4;
            if (piece < 4) cpa16(dst, src); else cpa8(dst, src);
        }
        uint32_t swb = s_w_b + buf * 5184 * 4;
        const unsigned* wsrc = wbase + (size_t)ch * 4608;
        for (int j = tid; j < 1152; j += 256) {
            int r = j >> 4, c4 = (j & 15) * 4;
            cpa16(swb + (r * 72 + c4) * 4, wsrc + j * 4);
        }
    };

    stage(0, 0);
    asm volatile("cp.async.commit_group;");
#pragma unroll 1
    for (int ch = 0; ch < NCH; ch++) {
        int cur = ch & 1;
        if (ch + 1 < NCH) stage(ch + 1, cur ^ 1);
        asm volatile("cp.async.commit_group;");
        asm volatile("cp.async.wait_group 1;");
        __syncthreads();
        const unsigned* bi = s_in + cur * 2880;
        const unsigned* bw = s_w + cur * 5184;
#pragma unroll
        for (int kappa = 0; kappa < 9; kappa++) {
            unsigned bf[4][2];
#pragma unroll
            for (int g = 0; g < 4; g++) {
                int ncol = warpN * 32 + g * 8 + lr;
                bf[g][0] = bw[kappa * 576 + lq * 72 + ncol];
                bf[g][1] = bw[kappa * 576 + (lq + 4) * 72 + ncol];
            }
            const int ky = kappa / 3, kx = kappa % 3;
#pragma unroll
            for (int f = 0; f < 4; f++) {
                const int base = (warpM * 4 + f + ky) * 20 + kx;
                unsigned a0 = bi[lq * 360 + base + lr];
                unsigned a1 = bi[lq * 360 + base + lr + 8];
                unsigned a2 = bi[(lq + 4) * 360 + base + lr];
                unsigned a3 = bi[(lq + 4) * 360 + base + lr + 8];
#pragma unroll
                for (int g = 0; g < 4; g++)
                    mma_f16(C[f][g], a0, a1, a2, a3, bf[g][0], bf[g][1]);
            }
        }
        __syncthreads();
    }

    // ---- epilogue: store + partial GN stats ----
    constexpr int G = OC / OCPG;
    float s0 = 0.f, q0 = 0.f, s1 = 0.f, q1 = 0.f;
#pragma unroll
    for (int f = 0; f < 4; f++) {
        const int gy = y0 + warpM * 4 + f;
#pragma unroll
        for (int g = 0; g < 4; g++) {
            const int oc = ocG * 64 + warpN * 32 + g * 8 + 2 * lq;
            const float b0 = bias[oc], b1v = bias[oc + 1];
            float v0 = C[f][g][0] + b0, v1 = C[f][g][1] + b1v;
            float v2 = C[f][g][2] + b0, v3 = C[f][g][3] + b1v;
            float* o0 = out + ((size_t)b * OC + oc) * HW + gy * 128 + x0;
            o0[lr] = v0; o0[HW + lr] = v1; o0[lr + 8] = v2; o0[HW + lr + 8] = v3;
            if (OCPG == 16 && g >= 2) {
                s1 += v0 + v1 + v2 + v3;
                q1 += v0 * v0 + v1 * v1 + v2 * v2 + v3 * v3;
            } else {
                s0 += v0 + v1 + v2 + v3;
                q0 += v0 * v0 + v1 * v1 + v2 * v2 + v3 * v3;
            }
        }
    }
#pragma unroll
    for (int o = 16; o; o >>= 1) {
        s0 += __shfl_xor_sync(0xffffffffu, s0, o);
        q0 += __shfl_xor_sync(0xffffffffu, q0, o);
        if (OCPG == 16) {
            s1 += __shfl_xor_sync(0xffffffffu, s1, o);
            q1 += __shfl_xor_sync(0xffffffffu, q1, o);
        }
    }
    if (lane == 0) {
        int gidx = (ocG * 64 + warpN * 32) / OCPG;
        atomicAdd(&part[(b * G + gidx) * 2],     s0);
        atomicAdd(&part[(b * G + gidx) * 2 + 1], q0);
        if (OCPG == 16) {
            atomicAdd(&part[(b * G + gidx + 1) * 2],     s1);
            atomicAdd(&part[(b * G + gidx + 1) * 2 + 1], q1);
        }
    }
}

// ------- GN+ReLU apply -> half2 pairs, interior only (padding stays 0) ------
template<int C_, int G>
__global__ void gn_apply(const float* __restrict__ t, const float* __restrict__ part,
                         const float* __restrict__ gw, const float* __restrict__ gb,
                         unsigned* __restrict__ outp)
{
    int p = blockIdx.x;                    // b*(C_/2) + cp
    int b = p / (C_ / 2), cp = p - b * (C_ / 2);
    int c0 = 2 * cp, c1 = c0 + 1;
    int g = c0 / (C_ / G);
    float n = (float)(C_ / G) * (float)HW;
    float S = part[(b * G + g) * 2], S2 = part[(b * G + g) * 2 + 1];
    float mean = S / n;
    float rs = rsqrtf(S2 / n - mean * mean + 1e-5f);
    float sc0 = rs * gw[c0], sh0 = gb[c0] - mean * sc0;
    float sc1 = rs * gw[c1], sh1 = gb[c1] - mean * sc1;
    const float* src0 = t + ((size_t)b * C_ + c0) * HW;
    const float* src1 = src0 + HW;
    unsigned* dst = outp + (size_t)p * PCH;
    for (int i = threadIdx.x; i < HW; i += 256) {
        int y = i >> 7, xx = i & 127;
        dst[(y + 1) * PR + xx + 1] = packh2(fmaxf(0.f, src0[i] * sc0 + sh0),
                                            fmaxf(0.f, src1[i] * sc1 + sh1));
    }
}

// ---------------- GN3+ReLU apply + transpose to [b][p][64] ------------------
__global__ void gn_apply3t(const float* __restrict__ g3w, const float* __restrict__ g3b) {
    __shared__ float smT[64 * 65];
    int b = blockIdx.y;
    int p0 = blockIdx.x * 64;
    int tid = threadIdx.x;
#pragma unroll
    for (int i = 0; i < 16; i++) {
        int idx = tid + i * 256;
        int c = idx >> 6, pl = idx & 63;
        int g = c >> 4;
        float S = g_part3[(b * 4 + g) * 2], S2 = g_part3[(b * 4 + g) * 2 + 1];
        float n = 16.f * (float)HW;
        float mean = S / n;
        float rs = rsqrtf(S2 / n - mean * mean + 1e-5f);
        float sc = rs * g3w[c], sh = g3b[c] - mean * sc;
        smT[c * 65 + pl] = fmaxf(0.f, g_t3[((size_t)b * 64 + c) * HW + p0 + pl] * sc + sh);
    }
    __syncthreads();
    float* dst = g_t3t + ((size_t)b * HW + p0) * 64;
#pragma unroll
    for (int i = 0; i < 16; i++) {
        int idx = tid + i * 256;
        int pl = idx >> 6, c = idx & 63;
        dst[pl * 64 + c] = smT[c * 65 + pl];
    }
}

// ---------------- masked segment-sum pooling --------------------------------
__global__ void pool_kernel(const int* __restrict__ masks) {
    __shared__ float s_sum[20][64];
    __shared__ float s_cnt[20];
    const int tid = threadIdx.x;
    const int lane = tid & 31, w = tid >> 5;
    const int b = blockIdx.y;
    const int base = blockIdx.x * 1024;

    for (int i = tid; i < 20 * 64; i += 256) ((float*)s_sum)[i] = 0.f;
    if (tid < 20) s_cnt[tid] = 0.f;
    __syncthreads();

    const int* mp = masks + b * HW + base;
    for (int p = w; p < 1024; p += 8) {
        int id = mp[p];
        if (id > 0) {
            const float* hp = g_t3t + ((size_t)b * HW + base + p) * 64;
            atomicAdd(&s_sum[id - 1][lane],      hp[lane]);
            atomicAdd(&s_sum[id - 1][lane + 32], hp[lane + 32]);
            if (lane == 0) atomicAdd(&s_cnt[id - 1], 1.f);
        }
    }
    __syncthreads();
    for (int i = tid; i < 20 * 64; i += 256) {
        int k = i >> 6, c = i & 63;
        atomicAdd(&g_sums[((size_t)b * 20 + k) * 64 + c], s_sum[k][c]);
    }
    if (tid < 20) atomicAdd(&g_cnts[b * 20 + tid], s_cnt[tid]);
}

// ---------------- heads ------------------------------------------------------
__global__ void head_kernel(const float* __restrict__ wb, const float* __restrict__ bb,
                            const float* __restrict__ wc, const float* __restrict__ bc,
                            float* __restrict__ out)
{
    int t = threadIdx.x;
    if (t >= 640) return;
    int b = t / 160;
    int rem = t - b * 160;
    int k = rem >> 3, o = rem & 7;
    float inv = 1.f / (g_cnts[b * 20 + k] + 1e-6f);
    const float* sp = &g_sums[((size_t)b * 20 + k) * 64];
    if (o < 7) {
        float s = bb[o];
        for (int c = 0; c < 64; c++) s += sp[c] * inv * wb[o * 64 + c];
        out[(b * 20 + k) * 7 + o] = s;
    } else {
        float s = bc[0];
        for (int c = 0; c < 64; c++) s += sp[c] * inv * wc[c];
        out[560 + b * 20 + k] = 1.f / (1.f + expf(-s));
    }
}

// ---------------- launch ----------------------------------------------------
extern "C" void kernel_launch(void* const* d_in, const int* in_sizes, int n_in,
                              void* d_out, int out_size)
{
    const float* x   = (const float*)d_in[0];
    const int*   mk  = (const int*)  d_in[1];
    const float* w1  = (const float*)d_in[2];
    const float* b1  = (const float*)d_in[3];
    const float* g1w = (const float*)d_in[4];
    const float* g1b = (const float*)d_in[5];
    const float* w2  = (const float*)d_in[6];
    const float* b2  = (const float*)d_in[7];
    const float* g2w = (const float*)d_in[8];
    const float* g2b = (const float*)d_in[9];
    const float* w3  = (const float*)d_in[10];
    const float* b3  = (const float*)d_in[11];
    const float* g3w = (const float*)d_in[12];
    const float* g3b = (const float*)d_in[13];
    const float* wb  = (const float*)d_in[14];
    const float* bb  = (const float*)d_in[15];
    const float* wc  = (const float*)d_in[16];
    const float* bc  = (const float*)d_in[17];
    float* out = (float*)d_out;

    unsigned *xp, *t1p, *t2p, *w1t, *w2t, *w3t;
    float *t1, *t2, *t3, *p1, *p2, *p3;
    cudaGetSymbolAddress((void**)&xp,  g_xp);
    cudaGetSymbolAddress((void**)&t1,  g_t1);
    cudaGetSymbolAddress((void**)&t1p, g_t1p);
    cudaGetSymbolAddress((void**)&t2,  g_t2);
    cudaGetSymbolAddress((void**)&t2p, g_t2p);
    cudaGetSymbolAddress((void**)&t3,  g_t3);
    cudaGetSymbolAddress((void**)&w1t, g_w1t);
    cudaGetSymbolAddress((void**)&w2t, g_w2t);
    cudaGetSymbolAddress((void**)&w3t, g_w3t);
    cudaGetSymbolAddress((void**)&p1,  g_part1);
    cudaGetSymbolAddress((void**)&p2,  g_part2);
    cudaGetSymbolAddress((void**)&p3,  g_part3);

    const int SMEMB = SMEM_WORDS * 4;
    cudaFuncSetAttribute(conv_mma<512, 256, 32>, cudaFuncAttributeMaxDynamicSharedMemorySize, SMEMB);
    cudaFuncSetAttribute(conv_mma<256, 128, 32>, cudaFuncAttributeMaxDynamicSharedMemorySize, SMEMB);
    cudaFuncSetAttribute(conv_mma<128, 64, 16>,  cudaFuncAttributeMaxDynamicSharedMemorySize, SMEMB);

    // merged prep: x-pack (1024) + w1 (2304) + w2 (576) + w3 (144) + zero (1)
    prep_all<<<4049, 256>>>(x, w1, w2, w3);

    conv_mma<512, 256, 32><<<dim3(64, 4, 4), 256, SMEMB>>>(xp, w1t, b1, t1, p1);
    gn_apply<256, 8><<<4 * 128, 256>>>(t1, p1, g1w, g1b, t1p);

    conv_mma<256, 128, 32><<<dim3(64, 2, 4), 256, SMEMB>>>(t1p, w2t, b2, t2, p2);
    gn_apply<128, 4><<<4 * 64, 256>>>(t2, p2, g2w, g2b, t2p);

    conv_mma<128, 64, 16><<<dim3(64, 1, 4), 256, SMEMB>>>(t2p, w3t, b3, t3, p3);
    gn_apply3t<<<dim3(256, 4), 256>>>(g3w, g3b);

    pool_kernel<<<dim3(16, 4), 256>>>(mk);
    head_kernel<<<1, 640>>>(wb, bb, wc, bc, out);
}